// round 1
// baseline (speedup 1.0000x reference)
#include <cuda_runtime.h>
#include <math.h>

#define NPTS    (1 << 20)
#define RESG    160
#define TILE    32
#define NTILES  (NPTS / TILE)
#define HS      36      // hidden tile row stride (floats): conflict-free STS.128, 16B-aligned
#define WT      132     // transposed big-weight row stride (floats): conflict-free + 16B-aligned

// ---- packed f32x2 FMA helpers (2 FMA per instruction; ptxas won't auto-fuse) ----
__device__ __forceinline__ unsigned long long fma2(unsigned long long a,
                                                   unsigned long long b,
                                                   unsigned long long c) {
    unsigned long long d;
    asm("fma.rn.f32x2 %0, %1, %2, %3;" : "=l"(d) : "l"(a), "l"(b), "l"(c));
    return d;
}
__device__ __forceinline__ unsigned long long dup2(float w) {
    unsigned long long d;
    asm("mov.b64 %0, {%1, %1};" : "=l"(d) : "f"(w), "f"(w));
    return d;
}

// Layer with small K, weights in [K][128] layout (scalar weight load, broadcast acts).
template <int K>
__device__ __forceinline__ void layer16(const float* __restrict__ in, int instride,
                                        const float* __restrict__ Wsm, float bias,
                                        int j, int po, float* outv) {
    unsigned long long acc[8];
#pragma unroll
    for (int m = 0; m < 8; m++) acc[m] = 0ull;
#pragma unroll 4
    for (int k = 0; k < K; k++) {
        unsigned long long wd = dup2(Wsm[k * 128 + j]);
        const ulonglong2* rp = (const ulonglong2*)(in + k * instride + po);
        ulonglong2 u0 = rp[0], u1 = rp[1];
        acc[0] = fma2(u0.x, wd, acc[0]);
        acc[1] = fma2(u0.y, wd, acc[1]);
        acc[2] = fma2(u1.x, wd, acc[2]);
        acc[3] = fma2(u1.y, wd, acc[3]);
        const ulonglong2* rq = rp + 2;
        ulonglong2 u2 = rq[0], u3 = rq[1];
        acc[4] = fma2(u2.x, wd, acc[4]);
        acc[5] = fma2(u2.y, wd, acc[5]);
        acc[6] = fma2(u3.x, wd, acc[6]);
        acc[7] = fma2(u3.y, wd, acc[7]);
    }
#pragma unroll
    for (int m = 0; m < 8; m++) {
        unsigned long long a = acc[m];
        float2 v = *reinterpret_cast<float2*>(&a);
        outv[2 * m]     = fmaxf(v.x + bias, 0.f);
        outv[2 * m + 1] = fmaxf(v.y + bias, 0.f);
    }
}

// K=128 layer with transposed weights [128][WT]: weight column as float4 stream.
__device__ __forceinline__ void layer16T(const float* __restrict__ in, int instride,
                                         const float* __restrict__ Wt, float bias,
                                         int j, int po, float* outv) {
    unsigned long long acc[8];
#pragma unroll
    for (int m = 0; m < 8; m++) acc[m] = 0ull;
    const float* wrow = Wt + j * WT;
#pragma unroll 2
    for (int k = 0; k < 128; k += 4) {
        float4 w4 = *(const float4*)(wrow + k);
        unsigned long long wd[4] = {dup2(w4.x), dup2(w4.y), dup2(w4.z), dup2(w4.w)};
#pragma unroll
        for (int kk = 0; kk < 4; kk++) {
            const ulonglong2* rp = (const ulonglong2*)(in + (k + kk) * instride + po);
            ulonglong2 u0 = rp[0], u1 = rp[1];
            acc[0] = fma2(u0.x, wd[kk], acc[0]);
            acc[1] = fma2(u0.y, wd[kk], acc[1]);
            acc[2] = fma2(u1.x, wd[kk], acc[2]);
            acc[3] = fma2(u1.y, wd[kk], acc[3]);
            const ulonglong2* rq = rp + 2;
            ulonglong2 u2 = rq[0], u3 = rq[1];
            acc[4] = fma2(u2.x, wd[kk], acc[4]);
            acc[5] = fma2(u2.y, wd[kk], acc[5]);
            acc[6] = fma2(u3.x, wd[kk], acc[6]);
            acc[7] = fma2(u3.y, wd[kk], acc[7]);
        }
    }
#pragma unroll
    for (int m = 0; m < 8; m++) {
        unsigned long long a = acc[m];
        float2 v = *reinterpret_cast<float2*>(&a);
        outv[2 * m]     = fmaxf(v.x + bias, 0.f);
        outv[2 * m + 1] = fmaxf(v.y + bias, 0.f);
    }
}

// Shared-memory budget (floats):
//  dW1 1536 | db1 128 | dW2t 16896 | db2 128 | dW3 128 | db3 4
//  rW1 5248 | rb1 128 | rW2t 16896 | rb2 128 | rW3 384 | rb3 4
//  rf 1312 | h1 4608 | hb 4608   -> total 52136 floats = 208544 bytes
#define SMEM_FLOATS 52136
#define SMEM_BYTES  (SMEM_FLOATS * 4)

__global__ void __launch_bounds__(256, 1) fastsurf_kernel(
    const float* __restrict__ x, const float* __restrict__ grid,
    const float* __restrict__ dW1, const float* __restrict__ db1,
    const float* __restrict__ dW2, const float* __restrict__ db2,
    const float* __restrict__ dW3, const float* __restrict__ db3,
    const float* __restrict__ rW1, const float* __restrict__ rb1,
    const float* __restrict__ rW2, const float* __restrict__ rb2,
    const float* __restrict__ rW3, const float* __restrict__ rb3,
    float* __restrict__ out) {
    extern __shared__ float sm[];
    float* s_dW1  = sm;                      // 1536
    float* s_db1  = s_dW1 + 12 * 128;        // 128
    float* s_dW2t = s_db1 + 128;             // 16896 (transposed [j][k], stride WT)
    float* s_db2  = s_dW2t + 128 * WT;       // 128
    float* s_dW3  = s_db2 + 128;             // 128
    float* s_db3  = s_dW3 + 128;             // 4
    float* s_rW1  = s_db3 + 4;               // 5248
    float* s_rb1  = s_rW1 + 41 * 128;        // 128
    float* s_rW2t = s_rb1 + 128;             // 16896
    float* s_rb2  = s_rW2t + 128 * WT;       // 128
    float* s_rW3  = s_rb2 + 128;             // 384
    float* s_rb3  = s_rW3 + 3 * 128;         // 4
    float* s_rf   = s_rb3 + 4;               // 41*32
    float* s_h1   = s_rf + 41 * 32;          // 128*HS
    float* s_hb   = s_h1 + 128 * HS;         // 128*HS

    const int tid = threadIdx.x;

    // ---- one-time weight staging ----
    for (int i = tid * 4; i < 1536; i += 1024) *(float4*)(s_dW1 + i) = *(const float4*)(dW1 + i);
    for (int i = tid * 4; i < 5248; i += 1024) *(float4*)(s_rW1 + i) = *(const float4*)(rW1 + i);
    for (int i = tid; i < 16384; i += 256) {   // transpose dW2 [k][j] -> [j][k]
        int k = i >> 7, jj = i & 127;
        s_dW2t[jj * WT + k] = dW2[i];
    }
    for (int i = tid; i < 16384; i += 256) {
        int k = i >> 7, jj = i & 127;
        s_rW2t[jj * WT + k] = rW2[i];
    }
    if (tid < 128) {
        s_db1[tid] = db1[tid];
        s_db2[tid] = db2[tid];
        s_dW3[tid] = dW3[tid];
        s_rb1[tid] = rb1[tid];
        s_rb2[tid] = rb2[tid];
        s_rW3[tid * 3 + 0] = rW3[tid * 3 + 0];
        s_rW3[tid * 3 + 1] = rW3[tid * 3 + 1];
        s_rW3[tid * 3 + 2] = rW3[tid * 3 + 2];
    }
    if (tid == 0) s_db3[0] = db3[0];
    if (tid < 3) s_rb3[tid] = rb3[tid];
    __syncthreads();

    const int j  = tid & 127;
    const int po = (tid >> 7) * 16;  // half 0: points 0..15, half 1: 16..31
    float hv[16];

    for (int tile = blockIdx.x; tile < NTILES; tile += gridDim.x) {
        const int base = tile * TILE;

        // ---- step 1: trilinear gather (8 threads/point) + view-embed/ff into rf ----
        {
            const int pp = tid >> 3, corner = tid & 7;
            const float* xp = x + (size_t)(base + pp) * 8;
            float px = fminf(fmaxf(xp[0], 0.f), 1.f);
            float py = fminf(fmaxf(xp[1], 0.f), 1.f);
            float pz = fminf(fmaxf(xp[2], 0.f), 1.f);
            float fx = px * 159.f, fy = py * 159.f, fz = pz * 159.f;
            float x0 = fminf(floorf(fx), 158.f);
            float y0 = fminf(floorf(fy), 158.f);
            float z0 = fminf(floorf(fz), 158.f);
            float wx = fx - x0, wy = fy - y0, wz = fz - z0;
            int xi = (int)x0 + ((corner >> 2) & 1);
            int yi = (int)y0 + ((corner >> 1) & 1);
            int zi = (int)z0 + (corner & 1);
            float wgt = ((corner & 4) ? wx : 1.f - wx) *
                        ((corner & 2) ? wy : 1.f - wy) *
                        ((corner & 1) ? wz : 1.f - wz);
            const float* gp = grid + (size_t)((xi * RESG + yi) * RESG + zi) * 12;
            float4 g0 = *(const float4*)gp;
            float4 g1 = *(const float4*)(gp + 4);
            float4 g2 = *(const float4*)(gp + 8);
            float v[12] = {g0.x, g0.y, g0.z, g0.w, g1.x, g1.y, g1.z, g1.w,
                           g2.x, g2.y, g2.z, g2.w};
#pragma unroll
            for (int c = 0; c < 12; c++) v[c] *= wgt;
#pragma unroll
            for (int off = 4; off; off >>= 1)
#pragma unroll
                for (int c = 0; c < 12; c++)
                    v[c] += __shfl_down_sync(0xffffffffu, v[c], off);
            if (corner == 0) {
#pragma unroll
                for (int c = 0; c < 12; c++) s_rf[c * 32 + pp] = v[c];
            } else if (corner <= 3) {
                int d = corner - 1;
                float vv = xp[5 + d];
                s_rf[(12 + d) * 32 + pp] = vv;
                float f = 1.f;
#pragma unroll
                for (int k = 0; k < 4; k++) {
                    s_rf[(15 + 6 * k + d) * 32 + pp]     = sinf(vv * f);
                    s_rf[(15 + 6 * k + 3 + d) * 32 + pp] = cosf(vv * f);
                    f *= 2.f;
                }
            } else if (corner == 4) {
                s_rf[39 * 32 + pp] = xp[3];
                s_rf[40 * 32 + pp] = xp[4];
            }
        }
        __syncthreads();

        // ---- density layer 1: 12 -> 128 ----
        layer16<12>(s_rf, 32, s_dW1, s_db1[j], j, po, hv);
#pragma unroll
        for (int p = 0; p < 16; p++) s_h1[j * HS + po + p] = hv[p];
        __syncthreads();

        // ---- density layer 2: 128 -> 128 ----
        layer16T(s_h1, HS, s_dW2t, s_db2[j], j, po, hv);
#pragma unroll
        for (int p = 0; p < 16; p++) s_hb[j * HS + po + p] = hv[p];
        __syncthreads();

        // ---- sdf head (warp 0) + rgb layer 1 (all): disjoint smem, no hazard ----
        if (tid < 32) {
            float s = s_db3[0];
#pragma unroll 8
            for (int k = 0; k < 128; k++) s += s_hb[k * HS + tid] * s_dW3[k];
            out[(size_t)(base + tid) * 4 + 3] = s;
        }
        layer16<41>(s_rf, 32, s_rW1, s_rb1[j], j, po, hv);
#pragma unroll
        for (int p = 0; p < 16; p++) s_h1[j * HS + po + p] = hv[p];
        __syncthreads();

        // ---- rgb layer 2: 128 -> 128 ----
        layer16T(s_h1, HS, s_rW2t, s_rb2[j], j, po, hv);
#pragma unroll
        for (int p = 0; p < 16; p++) s_hb[j * HS + po + p] = hv[p];
        __syncthreads();

        // ---- rgb head: 3 warps, one channel each ----
        if (tid < 96) {
            int pp = tid & 31, c = tid >> 5;
            float s = s_rb3[c];
#pragma unroll 8
            for (int k = 0; k < 128; k++) s += s_hb[k * HS + pp] * s_rW3[k * 3 + c];
            out[(size_t)(base + pp) * 4 + c] = s;
        }
        __syncthreads();
    }
}

extern "C" void kernel_launch(void* const* d_in, const int* in_sizes, int n_in,
                              void* d_out, int out_size) {
    (void)in_sizes; (void)n_in; (void)out_size;
    const float* x    = (const float*)d_in[0];
    const float* grid = (const float*)d_in[1];
    const float* dW1  = (const float*)d_in[2];
    const float* db1  = (const float*)d_in[3];
    const float* dW2  = (const float*)d_in[4];
    const float* db2  = (const float*)d_in[5];
    const float* dW3  = (const float*)d_in[6];
    const float* db3  = (const float*)d_in[7];
    const float* rW1  = (const float*)d_in[8];
    const float* rb1  = (const float*)d_in[9];
    const float* rW2  = (const float*)d_in[10];
    const float* rb2  = (const float*)d_in[11];
    const float* rW3  = (const float*)d_in[12];
    const float* rb3  = (const float*)d_in[13];
    float* out = (float*)d_out;

    int nsm = 152;
    cudaDeviceGetAttribute(&nsm, cudaDevAttrMultiProcessorCount, 0);
    cudaFuncSetAttribute(fastsurf_kernel,
                         cudaFuncAttributeMaxDynamicSharedMemorySize, SMEM_BYTES);
    fastsurf_kernel<<<nsm, 256, SMEM_BYTES>>>(x, grid, dW1, db1, dW2, db2, dW3, db3,
                                              rW1, rb1, rW2, rb2, rW3, rb3, out);
}